// round 7
// baseline (speedup 1.0000x reference)
#include <cuda_runtime.h>
#include <cuda_fp16.h>
#include <math.h>

// Fixed-capacity layout for n=512 (nm1=511), runtime nm1 still passed.
#define SP  516           // message plane row stride (even)
#define HS  512           // h-edge / plaq phi plane stride (even)
#define VS  516           // v-edge phi plane stride (even)
#define MROWS 514
#define MSZ (MROWS * SP)

// fp16 storage, fp32 compute. All planes 16B aligned; even strides give
// aligned uint4 (LDG.128) access for column pairs.
// plane0/1: slot0/1 messages at q=(i+1)*SP+j+2.
// plane2: slot2 stored at q-1 (so readers load right-neighbor slot2 at q).
// plane3: slot3 stored at q+1 (so readers load left-neighbor slot3 at q).
__device__ __align__(16) uint2 g_Mh[2][4][MSZ];
__device__ __align__(16) uint2 g_phiEh_h[512 * HS];        // h-edge (i,j): i*HS+j
__device__ __align__(16) uint2 g_phiEh_v[511 * VS + 8];    // v-edge (i,j): i*VS+j
__device__ uint4 g_phiPh[2][511 * HS];                     // plaq phi halves: i*HS+j
__device__ double g_F;

// ---------------------------------------------------------------------------
__device__ __forceinline__ float4 h4_to_f4(uint2 v) {
    union { unsigned u; __half2 h; } a, b;
    a.u = v.x; b.u = v.y;
    float2 fa = __half22float2(a.h), fb = __half22float2(b.h);
    return make_float4(fa.x, fa.y, fb.x, fb.y);
}
__device__ __forceinline__ uint2 f4_to_h4(float4 f) {
    union { unsigned u; __half2 h; } a, b;
    a.h = __floats2half2_rn(f.x, f.y);
    b.h = __floats2half2_rn(f.z, f.w);
    return make_uint2(a.u, b.u);
}
__device__ __forceinline__ uint2 lo4(uint4 v) { return make_uint2(v.x, v.y); }
__device__ __forceinline__ uint2 hi4(uint4 v) { return make_uint2(v.z, v.w); }

__device__ __forceinline__ float fast_logf(float x) {
    int ix = __float_as_int(x);
    int ex = (ix >> 23) - 127;
    float m = __int_as_float((ix & 0x007FFFFF) | 0x3F800000);
    if (m > 1.41421356f) { m *= 0.5f; ex += 1; }
    float f = m - 1.0f;
    float z = f * f;
    float p = 7.0376836292e-2f;
    p = fmaf(p, f, -1.1514610310e-1f);
    p = fmaf(p, f,  1.1676998740e-1f);
    p = fmaf(p, f, -1.2420140846e-1f);
    p = fmaf(p, f,  1.4249322787e-1f);
    p = fmaf(p, f, -1.6668057665e-1f);
    p = fmaf(p, f,  2.0000714765e-1f);
    p = fmaf(p, f, -2.4999993993e-1f);
    p = fmaf(p, f,  3.3333331174e-1f);
    p = p * z * f;
    p = fmaf(-0.5f, z, p);
    return fmaf((float)ex, 0.693147180559945f, f + p);
}

__device__ __forceinline__ float pow2_inv_scale(float Z) {
    int eb = (__float_as_int(Z) >> 23) & 0xFF;
    return __int_as_float((254 - eb) << 23);
}

__device__ __forceinline__ void block_add_F(float v) {
    #pragma unroll
    for (int o = 16; o; o >>= 1) v += __shfl_down_sync(0xffffffffu, v, o);
    __shared__ float sh[32];
    int lane = threadIdx.x & 31, w = threadIdx.x >> 5;
    if (lane == 0) sh[w] = v;
    __syncthreads();
    if (w == 0) {
        int nw = (blockDim.x + 31) >> 5;
        float s = (lane < nw) ? sh[lane] : 0.0f;
        #pragma unroll
        for (int o = 16; o; o >>= 1) s += __shfl_down_sync(0xffffffffu, s, o);
        if (lane == 0) atomicAdd(&g_F, (double)s);
    }
}

__device__ __forceinline__ float4 exp4(float4 v) {
    return make_float4(__expf(v.x), __expf(v.y), __expf(v.z), __expf(v.w));
}
__device__ __forceinline__ float4 mul4(float4 a, float4 b) {
    return make_float4(a.x * b.x, a.y * b.y, a.z * b.z, a.w * b.w);
}

__device__ __forceinline__ void phi_unpack(uint4 a, uint4 b, float Phi[16]) {
    float4 x = h4_to_f4(make_uint2(a.x, a.y));
    float4 y = h4_to_f4(make_uint2(a.z, a.w));
    float4 z = h4_to_f4(make_uint2(b.x, b.y));
    float4 w = h4_to_f4(make_uint2(b.z, b.w));
    Phi[0]=x.x; Phi[1]=x.y; Phi[2]=x.z; Phi[3]=x.w;
    Phi[4]=y.x; Phi[5]=y.y; Phi[6]=y.z; Phi[7]=y.w;
    Phi[8]=z.x; Phi[9]=z.y; Phi[10]=z.z; Phi[11]=z.w;
    Phi[12]=w.x; Phi[13]=w.y; Phi[14]=w.z; Phi[15]=w.w;
}

// Core 16-state update -> 4 normalized fp16 messages.
__device__ __forceinline__ void plaq_core(
    float4 N0, float4 N1, float4 N2, float4 N3, const float Phi[16], uint2 m[4])
{
    float n0[4] = {N0.x, N0.y, N0.z, N0.w};
    float n1[4] = {N1.x, N1.y, N1.z, N1.w};
    float n2[4] = {N2.x, N2.y, N2.z, N2.w};
    float n3[4] = {N3.x, N3.y, N3.z, N3.w};
    float u0[4] = {0,0,0,0}, u1[4] = {0,0,0,0}, u2[4] = {0,0,0,0}, u3[4] = {0,0,0,0};
    #pragma unroll
    for (int a = 0; a < 2; a++)
    #pragma unroll
    for (int b = 0; b < 2; b++)
    #pragma unroll
    for (int c = 0; c < 2; c++)
    #pragma unroll
    for (int d = 0; d < 2; d++) {
        int idx = a * 8 + b * 4 + c * 2 + d;
        float ph = Phi[idx];
        float va = n0[a * 2 + b], vb = n1[c * 2 + d];
        float vc = n2[a * 2 + c], vd = n3[b * 2 + d];
        float q1 = ph * vc * vd;
        u0[a * 2 + b] = fmaf(q1, vb, u0[a * 2 + b]);
        u1[c * 2 + d] = fmaf(q1, va, u1[c * 2 + d]);
        float q2 = ph * va * vb;
        u2[a * 2 + c] = fmaf(q2, vd, u2[a * 2 + c]);
        u3[b * 2 + d] = fmaf(q2, vc, u3[b * 2 + d]);
    }
    {
        float Z = (u0[0]+u0[1]) + (u0[2]+u0[3]); float s = pow2_inv_scale(Z);
        m[0] = f4_to_h4(make_float4(u0[0]*s, u0[1]*s, u0[2]*s, u0[3]*s));
    }
    {
        float Z = (u1[0]+u1[1]) + (u1[2]+u1[3]); float s = pow2_inv_scale(Z);
        m[1] = f4_to_h4(make_float4(u1[0]*s, u1[1]*s, u1[2]*s, u1[3]*s));
    }
    {
        float Z = (u2[0]+u2[1]) + (u2[2]+u2[3]); float s = pow2_inv_scale(Z);
        m[2] = f4_to_h4(make_float4(u2[0]*s, u2[1]*s, u2[2]*s, u2[3]*s));
    }
    {
        float Z = (u3[0]+u3[1]) + (u3[2]+u3[3]); float s = pow2_inv_scale(Z);
        m[3] = f4_to_h4(make_float4(u3[0]*s, u3[1]*s, u3[2]*s, u3[3]*s));
    }
}

// ---------------------------------------------------------------------------
// One row of the ILP-4 iteration: plaquettes (i, j0) and (i, j0+1).
template<int SRC>
__device__ __forceinline__ void iter_row(int i, int j0, bool jok,
                                         uint4 hT, uint4 hB)
{
    constexpr int DST = SRC ^ 1;
    int q = (i + 1) * SP + j0 + 2;   // even
    uint4 r1 = __ldg((const uint4*)&g_Mh[SRC][1][q - SP]);
    uint4 r0 = __ldg((const uint4*)&g_Mh[SRC][0][q + SP]);
    uint4 r2 = __ldg((const uint4*)&g_Mh[SRC][2][q]);   // right slot2 (shifted)
    uint4 r3 = __ldg((const uint4*)&g_Mh[SRC][3][q]);   // left slot3 (shifted)
    uint4 ve  = __ldg((const uint4*)&g_phiEh_v[i * VS + j0]);
    uint2 ve2 = __ldg(&g_phiEh_v[i * VS + j0 + 2]);
    uint4 pa0 = __ldg(&g_phiPh[0][i * HS + j0]);
    uint4 pa1 = __ldg(&g_phiPh[1][i * HS + j0]);
    uint4 pb0 = __ldg(&g_phiPh[0][i * HS + j0 + 1]);
    uint4 pb1 = __ldg(&g_phiPh[1][i * HS + j0 + 1]);

    uint2 mA[4];
    {
        float Phi[16]; phi_unpack(pa0, pa1, Phi);
        float4 N0 = mul4(h4_to_f4(lo4(hT)), h4_to_f4(lo4(r1)));
        float4 N1 = mul4(h4_to_f4(lo4(hB)), h4_to_f4(lo4(r0)));
        float4 N2 = mul4(h4_to_f4(lo4(ve)), h4_to_f4(lo4(r3)));
        float4 N3 = mul4(h4_to_f4(hi4(ve)), h4_to_f4(lo4(r2)));
        plaq_core(N0, N1, N2, N3, Phi, mA);
    }
    if (jok) {
        uint2 mB[4];
        float Phi[16]; phi_unpack(pb0, pb1, Phi);
        float4 N0 = mul4(h4_to_f4(hi4(hT)), h4_to_f4(hi4(r1)));
        float4 N1 = mul4(h4_to_f4(hi4(hB)), h4_to_f4(hi4(r0)));
        float4 N2 = mul4(h4_to_f4(hi4(ve)), h4_to_f4(hi4(r3)));
        float4 N3 = mul4(h4_to_f4(ve2),     h4_to_f4(hi4(r2)));
        plaq_core(N0, N1, N2, N3, Phi, mB);
        *(uint4*)&g_Mh[DST][0][q] = make_uint4(mA[0].x, mA[0].y, mB[0].x, mB[0].y);
        *(uint4*)&g_Mh[DST][1][q] = make_uint4(mA[1].x, mA[1].y, mB[1].x, mB[1].y);
        g_Mh[DST][2][q - 1] = mA[2]; g_Mh[DST][2][q]     = mB[2];
        g_Mh[DST][3][q + 1] = mA[3]; g_Mh[DST][3][q + 2] = mB[3];
    } else {
        g_Mh[DST][0][q]     = mA[0];
        g_Mh[DST][1][q]     = mA[1];
        g_Mh[DST][2][q - 1] = mA[2];
        g_Mh[DST][3][q + 1] = mA[3];
    }
}

template<int SRC>
__global__ void __launch_bounds__(128) k_iter4(int nm1) {
    int jp = blockIdx.x * blockDim.x + threadIdx.x;
    int j0 = jp * 2;
    if (j0 >= nm1) return;
    bool jok = (j0 + 1) < nm1;
    int i0 = blockIdx.y * 2;
    uint4 hT = __ldg((const uint4*)&g_phiEh_h[i0 * HS + j0]);
    uint4 hM = __ldg((const uint4*)&g_phiEh_h[(i0 + 1) * HS + j0]);
    iter_row<SRC>(i0, j0, jok, hT, hM);
    if (i0 + 1 < nm1) {
        uint4 hBt = __ldg((const uint4*)&g_phiEh_h[(i0 + 2) * HS + j0]);
        iter_row<SRC>(i0 + 1, j0, jok, hM, hBt);
    }
}

// ---------------------------------------------------------------------------
// Fused setup + iteration 1 -> buf 0.  Writes padded fp16 phi tables.
// Last grid.y row: pads + F=0.
__global__ void __launch_bounds__(128) k_first(
    const float4* __restrict__ lpp, const float4* __restrict__ lpe, int nm1)
{
    if (blockIdx.y == gridDim.y - 1) {
        int tot = gridDim.x * blockDim.x;
        int t = blockIdx.x * blockDim.x + threadIdx.x;
        if (t == 0) g_F = 0.0;
        uint2 one = f4_to_h4(make_float4(1.f, 1.f, 1.f, 1.f));
        for (int v = t; v < SP; v += tot) {
            #pragma unroll
            for (int b = 0; b < 2; b++) {
                g_Mh[b][0][(nm1 + 1) * SP + v] = one;   // bottom pad row
                g_Mh[b][1][v] = one;                    // top pad row
                if (v >= 1 && v <= nm1) {
                    g_Mh[b][2][v * SP + nm1 + 1] = one; // right pad col (slot2)
                    g_Mh[b][3][v * SP + 2] = one;       // left pad col (slot3)
                }
            }
        }
        return;
    }

    int pj = blockIdx.x * blockDim.x + threadIdx.x;
    int i0 = blockIdx.y * 2;
    if (pj >= nm1) return;
    int n = nm1 + 1, nH = n * nm1;
    bool iok = (i0 + 1) < nm1;
    int i1 = iok ? i0 + 1 : i0;

    float4 fT  = exp4(__ldg(&lpe[i0 * nm1 + pj]));
    float4 fM  = exp4(__ldg(&lpe[(i0 + 1) * nm1 + pj]));
    float4 fB  = iok ? exp4(__ldg(&lpe[(i0 + 2) * nm1 + pj])) : fM;
    float4 fLA = exp4(__ldg(&lpe[nH + i0 * n + pj]));
    float4 fRA = exp4(__ldg(&lpe[nH + i0 * n + pj + 1]));
    float4 fLB = iok ? exp4(__ldg(&lpe[nH + i1 * n + pj])) : fLA;
    float4 fRB = iok ? exp4(__ldg(&lpe[nH + i1 * n + pj + 1])) : fRA;

    // padded fp16 phi writes (ownership: h rows i0,i0+1; v left edges; right border)
    g_phiEh_h[i0 * HS + pj] = f4_to_h4(fT);
    g_phiEh_h[(i0 + 1) * HS + pj] = f4_to_h4(fM);
    g_phiEh_v[i0 * VS + pj] = f4_to_h4(fLA);
    if (iok) g_phiEh_v[i1 * VS + pj] = f4_to_h4(fLB);
    if (pj == nm1 - 1) {
        g_phiEh_v[i0 * VS + nm1] = f4_to_h4(fRA);
        if (iok) g_phiEh_v[i1 * VS + nm1] = f4_to_h4(fRB);
    }

    {   // plaq (i0, pj)
        float Phi[16];
        float4 a = exp4(__ldg(&lpp[(i0 * nm1 + pj) * 4 + 0]));
        float4 b = exp4(__ldg(&lpp[(i0 * nm1 + pj) * 4 + 1]));
        float4 c = exp4(__ldg(&lpp[(i0 * nm1 + pj) * 4 + 2]));
        float4 d = exp4(__ldg(&lpp[(i0 * nm1 + pj) * 4 + 3]));
        Phi[0]=a.x; Phi[1]=a.y; Phi[2]=a.z; Phi[3]=a.w;
        Phi[4]=b.x; Phi[5]=b.y; Phi[6]=b.z; Phi[7]=b.w;
        Phi[8]=c.x; Phi[9]=c.y; Phi[10]=c.z; Phi[11]=c.w;
        Phi[12]=d.x; Phi[13]=d.y; Phi[14]=d.z; Phi[15]=d.w;
        uint2 h0 = f4_to_h4(a), h1 = f4_to_h4(b), h2 = f4_to_h4(c), h3 = f4_to_h4(d);
        g_phiPh[0][i0 * HS + pj] = make_uint4(h0.x, h0.y, h1.x, h1.y);
        g_phiPh[1][i0 * HS + pj] = make_uint4(h2.x, h2.y, h3.x, h3.y);
        uint2 m[4];
        plaq_core(fT, fM, fLA, fRA, Phi, m);
        int q = (i0 + 1) * SP + pj + 2;
        g_Mh[0][0][q] = m[0]; g_Mh[0][1][q] = m[1];
        g_Mh[0][2][q - 1] = m[2]; g_Mh[0][3][q + 1] = m[3];
    }
    if (iok) {   // plaq (i1, pj)
        float Phi[16];
        float4 a = exp4(__ldg(&lpp[(i1 * nm1 + pj) * 4 + 0]));
        float4 b = exp4(__ldg(&lpp[(i1 * nm1 + pj) * 4 + 1]));
        float4 c = exp4(__ldg(&lpp[(i1 * nm1 + pj) * 4 + 2]));
        float4 d = exp4(__ldg(&lpp[(i1 * nm1 + pj) * 4 + 3]));
        Phi[0]=a.x; Phi[1]=a.y; Phi[2]=a.z; Phi[3]=a.w;
        Phi[4]=b.x; Phi[5]=b.y; Phi[6]=b.z; Phi[7]=b.w;
        Phi[8]=c.x; Phi[9]=c.y; Phi[10]=c.z; Phi[11]=c.w;
        Phi[12]=d.x; Phi[13]=d.y; Phi[14]=d.z; Phi[15]=d.w;
        uint2 h0 = f4_to_h4(a), h1 = f4_to_h4(b), h2 = f4_to_h4(c), h3 = f4_to_h4(d);
        g_phiPh[0][i1 * HS + pj] = make_uint4(h0.x, h0.y, h1.x, h1.y);
        g_phiPh[1][i1 * HS + pj] = make_uint4(h2.x, h2.y, h3.x, h3.y);
        uint2 m[4];
        plaq_core(fM, fB, fLB, fRB, Phi, m);
        int q = (i1 + 1) * SP + pj + 2;
        g_Mh[0][0][q] = m[0]; g_Mh[0][1][q] = m[1];
        g_Mh[0][2][q - 1] = m[2]; g_Mh[0][3][q + 1] = m[3];
    }
}

// ---------------------------------------------------------------------------
// Fused finals (reads buf0): h-edge belief, v-edge belief, plaquette F term.
__global__ void k_final(int nm1, const float4* __restrict__ lpe,
                        float* __restrict__ out) {
    int j = blockIdx.x * blockDim.x + threadIdx.x;
    int i = blockIdx.y;
    int n = nm1 + 1, nH = n * nm1;
    float fterm = 0.0f;
    if (j < n) {
        int q = (i + 1) * SP + j + 2;
        float4 m_h0 = h4_to_f4(__ldg(&g_Mh[0][0][q]));
        float4 m_h1 = h4_to_f4(__ldg(&g_Mh[0][1][q - SP]));
        float4 m_v0 = h4_to_f4(__ldg(&g_Mh[0][2][q - 1]));
        float4 m_v1 = h4_to_f4(__ldg(&g_Mh[0][3][q]));
        int outB = 1 + 2 * n * n;

        if (j < nm1) {
            int e = i * nm1 + j;
            float4 lp = __ldg(&lpe[e]);
            float4 pe = exp4(lp);
            float tx = pe.x * m_h0.x * m_h1.x, ty = pe.y * m_h0.y * m_h1.y;
            float tz = pe.z * m_h0.z * m_h1.z, tw = pe.w * m_h0.w * m_h1.w;
            float Z = (tx + ty) + (tz + tw);
            float inv = __fdividef(1.0f, Z);
            float bx = tx * inv, by = ty * inv, bz = tz * inv, bw = tw * inv;
            int base = outB + e * 4;
            out[base + 0] = bx; out[base + 1] = by; out[base + 2] = bz; out[base + 3] = bw;
            if (i > 0 && i < nm1) {
                fterm -= bx * (fast_logf(tx) - lp.x) + by * (fast_logf(ty) - lp.y)
                       + bz * (fast_logf(tz) - lp.z) + bw * (fast_logf(tw) - lp.w)
                       - fast_logf(Z);
            }
        }
        if (i < nm1) {
            int e = nH + i * n + j;
            float4 lp = __ldg(&lpe[e]);
            float4 pe = exp4(lp);
            float tx = pe.x * m_v0.x * m_v1.x, ty = pe.y * m_v0.y * m_v1.y;
            float tz = pe.z * m_v0.z * m_v1.z, tw = pe.w * m_v0.w * m_v1.w;
            float Z = (tx + ty) + (tz + tw);
            float inv = __fdividef(1.0f, Z);
            float bx = tx * inv, by = ty * inv, bz = tz * inv, bw = tw * inv;
            int base = outB + e * 4;
            out[base + 0] = bx; out[base + 1] = by; out[base + 2] = bz; out[base + 3] = bw;
            if (j > 0 && j < nm1) {
                fterm -= bx * (fast_logf(tx) - lp.x) + by * (fast_logf(ty) - lp.y)
                       + bz * (fast_logf(tz) - lp.z) + bw * (fast_logf(tw) - lp.w)
                       - fast_logf(Z);
            }
        }
        if (i < nm1 && j < nm1) {
            float4 N0 = mul4(h4_to_f4(__ldg(&g_phiEh_h[i * HS + j])),       m_h1);
            float4 N1 = mul4(h4_to_f4(__ldg(&g_phiEh_h[(i + 1) * HS + j])),
                             h4_to_f4(__ldg(&g_Mh[0][0][q + SP])));
            float4 N2 = mul4(h4_to_f4(__ldg(&g_phiEh_v[i * VS + j])),       m_v1);
            float4 N3 = mul4(h4_to_f4(__ldg(&g_phiEh_v[i * VS + j + 1])),
                             h4_to_f4(__ldg(&g_Mh[0][2][q])));
            float n0[4] = {N0.x, N0.y, N0.z, N0.w};
            float n1[4] = {N1.x, N1.y, N1.z, N1.w};
            float n2[4] = {N2.x, N2.y, N2.z, N2.w};
            float n3[4] = {N3.x, N3.y, N3.z, N3.w};
            float Phi[16];
            phi_unpack(__ldg(&g_phiPh[0][i * HS + j]), __ldg(&g_phiPh[1][i * HS + j]), Phi);

            float t0[4] = {0,0,0,0}, t1[4] = {0,0,0,0}, t2[4] = {0,0,0,0}, t3[4] = {0,0,0,0};
            #pragma unroll
            for (int a = 0; a < 2; a++)
            #pragma unroll
            for (int b = 0; b < 2; b++)
            #pragma unroll
            for (int c = 0; c < 2; c++)
            #pragma unroll
            for (int d = 0; d < 2; d++) {
                int idx = a * 8 + b * 4 + c * 2 + d;
                float ev = Phi[idx] * n0[a * 2 + b] * n1[c * 2 + d]
                                    * n2[a * 2 + c] * n3[b * 2 + d];
                t0[a * 2 + b] += ev; t1[c * 2 + d] += ev;
                t2[a * 2 + c] += ev; t3[b * 2 + d] += ev;
            }
            float sumE = (t0[0] + t0[1]) + (t0[2] + t0[3]);
            float acc = 0.0f;
            #pragma unroll
            for (int x = 0; x < 4; x++) {
                acc = fmaf(t0[x], fast_logf(n0[x]), acc);
                acc = fmaf(t1[x], fast_logf(n1[x]), acc);
                acc = fmaf(t2[x], fast_logf(n2[x]), acc);
                acc = fmaf(t3[x], fast_logf(n3[x]), acc);
            }
            fterm += __fdividef(acc, sumE) - fast_logf(sumE);
        }
    }
    block_add_F(fterm);
}

// ---------------------------------------------------------------------------
__global__ void k_node(float* __restrict__ out, int n) {
    int j = blockIdx.x * blockDim.x + threadIdx.x;
    int i = blockIdx.y;
    if (i == 0 && j == 0) out[0] = (float)(-g_F);
    if (j >= n) return;
    int nm1 = n - 1, nH = n * nm1;
    const float* B = out + 1 + 2 * n * n;
    float s0 = 0.f, s1 = 0.f; int deg = 0;
    if (j < nm1) { const float* b = B + (i * nm1 + j) * 4;          s0 += b[0] + b[1]; s1 += b[2] + b[3]; deg++; }
    if (j > 0)   { const float* b = B + (i * nm1 + j - 1) * 4;      s0 += b[0] + b[2]; s1 += b[1] + b[3]; deg++; }
    if (i < nm1) { const float* b = B + (nH + i * n + j) * 4;       s0 += b[0] + b[1]; s1 += b[2] + b[3]; deg++; }
    if (i > 0)   { const float* b = B + (nH + (i - 1) * n + j) * 4; s0 += b[0] + b[2]; s1 += b[1] + b[3]; deg++; }
    float invd = __fdividef(1.0f, (float)deg);
    int v = i * n + j;
    out[1 + v * 2 + 0] = s0 * invd;
    out[1 + v * 2 + 1] = s1 * invd;
}

// ---------------------------------------------------------------------------
extern "C" void kernel_launch(void* const* d_in, const int* in_sizes, int n_in,
                              void* d_out, int out_size) {
    const float* log_phi_plaq = (const float*)d_in[0];
    const float* log_phi_edge = (const float*)d_in[1];

    int P = in_sizes[0] / 16;
    int nm1 = (int)lrint(sqrt((double)P));
    int n = nm1 + 1;
    (void)n_in; (void)out_size;
    float* out = (float*)d_out;

    dim3 bs(128);
    dim3 grF((nm1 + 127) / 128, (nm1 + 1) / 2 + 1);  // +1 row for pads
    int pairs = (nm1 + 1) / 2;
    dim3 gr4((pairs + 127) / 128, pairs);

    // iter 1 (fused with setup) -> buf 0
    k_first<<<grF, bs>>>((const float4*)log_phi_plaq, (const float4*)log_phi_edge, nm1);
    // iters 2..5: 0->1, 1->0, 0->1, 1->0  (final state in buf 0)
    k_iter4<0><<<gr4, bs>>>(nm1);
    k_iter4<1><<<gr4, bs>>>(nm1);
    k_iter4<0><<<gr4, bs>>>(nm1);
    k_iter4<1><<<gr4, bs>>>(nm1);

    k_final<<<dim3((n + 127) / 128, n), 128>>>(nm1, (const float4*)log_phi_edge, out);
    k_node<<<dim3((n + 127) / 128, n), 128>>>(out, n);
}

// round 8
// speedup vs baseline: 1.0522x; 1.0522x over previous
#include <cuda_runtime.h>
#include <cuda_fp16.h>
#include <math.h>

// Fixed-capacity layout for n=512 (nm1=511), runtime nm1 still passed.
#define SP  516           // message plane row stride (even)
#define HS  512           // h-edge / plaq phi plane stride (even)
#define VS  516           // v-edge phi plane stride (even)
#define MROWS 514
#define MSZ (MROWS * SP)

// fp16 storage, fp32 compute. All planes 16B aligned; even strides give
// aligned uint4 (LDG.128) access for column pairs.
// plane0/1: slot0/1 messages at q=(i+1)*SP+j+2.
// plane2: slot2 stored at q-1 (readers load right-neighbor slot2 at q).
// plane3: slot3 stored at q+1 (readers load left-neighbor slot3 at q).
__device__ __align__(16) uint2 g_Mh[2][4][MSZ];
__device__ __align__(16) uint2 g_phiEh_h[512 * HS];        // h-edge (i,j): i*HS+j
__device__ __align__(16) uint2 g_phiEh_v[511 * VS + 8];    // v-edge (i,j): i*VS+j
__device__ uint4 g_phiPh[2][511 * HS];                     // plaq phi halves: i*HS+j
__device__ double g_F;

// ---------------------------------------------------------------------------
__device__ __forceinline__ float4 h4_to_f4(uint2 v) {
    union { unsigned u; __half2 h; } a, b;
    a.u = v.x; b.u = v.y;
    float2 fa = __half22float2(a.h), fb = __half22float2(b.h);
    return make_float4(fa.x, fa.y, fb.x, fb.y);
}
__device__ __forceinline__ uint2 f4_to_h4(float4 f) {
    union { unsigned u; __half2 h; } a, b;
    a.h = __floats2half2_rn(f.x, f.y);
    b.h = __floats2half2_rn(f.z, f.w);
    return make_uint2(a.u, b.u);
}
__device__ __forceinline__ uint2 lo4(uint4 v) { return make_uint2(v.x, v.y); }
__device__ __forceinline__ uint2 hi4(uint4 v) { return make_uint2(v.z, v.w); }

__device__ __forceinline__ float fast_logf(float x) {
    int ix = __float_as_int(x);
    int ex = (ix >> 23) - 127;
    float m = __int_as_float((ix & 0x007FFFFF) | 0x3F800000);
    if (m > 1.41421356f) { m *= 0.5f; ex += 1; }
    float f = m - 1.0f;
    float z = f * f;
    float p = 7.0376836292e-2f;
    p = fmaf(p, f, -1.1514610310e-1f);
    p = fmaf(p, f,  1.1676998740e-1f);
    p = fmaf(p, f, -1.2420140846e-1f);
    p = fmaf(p, f,  1.4249322787e-1f);
    p = fmaf(p, f, -1.6668057665e-1f);
    p = fmaf(p, f,  2.0000714765e-1f);
    p = fmaf(p, f, -2.4999993993e-1f);
    p = fmaf(p, f,  3.3333331174e-1f);
    p = p * z * f;
    p = fmaf(-0.5f, z, p);
    return fmaf((float)ex, 0.693147180559945f, f + p);
}

__device__ __forceinline__ float pow2_inv_scale(float Z) {
    int eb = (__float_as_int(Z) >> 23) & 0xFF;
    return __int_as_float((254 - eb) << 23);
}

__device__ __forceinline__ void block_add_F(float v) {
    #pragma unroll
    for (int o = 16; o; o >>= 1) v += __shfl_down_sync(0xffffffffu, v, o);
    __shared__ float sh[32];
    int lane = threadIdx.x & 31, w = threadIdx.x >> 5;
    if (lane == 0) sh[w] = v;
    __syncthreads();
    if (w == 0) {
        int nw = (blockDim.x + 31) >> 5;
        float s = (lane < nw) ? sh[lane] : 0.0f;
        #pragma unroll
        for (int o = 16; o; o >>= 1) s += __shfl_down_sync(0xffffffffu, s, o);
        if (lane == 0) atomicAdd(&g_F, (double)s);
    }
}

__device__ __forceinline__ float4 exp4(float4 v) {
    return make_float4(__expf(v.x), __expf(v.y), __expf(v.z), __expf(v.w));
}
__device__ __forceinline__ float4 mul4(float4 a, float4 b) {
    return make_float4(a.x * b.x, a.y * b.y, a.z * b.z, a.w * b.w);
}

__device__ __forceinline__ void phi_unpack(uint4 a, uint4 b, float Phi[16]) {
    float4 x = h4_to_f4(make_uint2(a.x, a.y));
    float4 y = h4_to_f4(make_uint2(a.z, a.w));
    float4 z = h4_to_f4(make_uint2(b.x, b.y));
    float4 w = h4_to_f4(make_uint2(b.z, b.w));
    Phi[0]=x.x; Phi[1]=x.y; Phi[2]=x.z; Phi[3]=x.w;
    Phi[4]=y.x; Phi[5]=y.y; Phi[6]=y.z; Phi[7]=y.w;
    Phi[8]=z.x; Phi[9]=z.y; Phi[10]=z.z; Phi[11]=z.w;
    Phi[12]=w.x; Phi[13]=w.y; Phi[14]=w.z; Phi[15]=w.w;
}

// Core 16-state update -> 4 normalized fp16 messages.
__device__ __forceinline__ void plaq_core(
    float4 N0, float4 N1, float4 N2, float4 N3, const float Phi[16], uint2 m[4])
{
    float n0[4] = {N0.x, N0.y, N0.z, N0.w};
    float n1[4] = {N1.x, N1.y, N1.z, N1.w};
    float n2[4] = {N2.x, N2.y, N2.z, N2.w};
    float n3[4] = {N3.x, N3.y, N3.z, N3.w};
    float u0[4] = {0,0,0,0}, u1[4] = {0,0,0,0}, u2[4] = {0,0,0,0}, u3[4] = {0,0,0,0};
    #pragma unroll
    for (int a = 0; a < 2; a++)
    #pragma unroll
    for (int b = 0; b < 2; b++)
    #pragma unroll
    for (int c = 0; c < 2; c++)
    #pragma unroll
    for (int d = 0; d < 2; d++) {
        int idx = a * 8 + b * 4 + c * 2 + d;
        float ph = Phi[idx];
        float va = n0[a * 2 + b], vb = n1[c * 2 + d];
        float vc = n2[a * 2 + c], vd = n3[b * 2 + d];
        float q1 = ph * vc * vd;
        u0[a * 2 + b] = fmaf(q1, vb, u0[a * 2 + b]);
        u1[c * 2 + d] = fmaf(q1, va, u1[c * 2 + d]);
        float q2 = ph * va * vb;
        u2[a * 2 + c] = fmaf(q2, vd, u2[a * 2 + c]);
        u3[b * 2 + d] = fmaf(q2, vc, u3[b * 2 + d]);
    }
    {
        float Z = (u0[0]+u0[1]) + (u0[2]+u0[3]); float s = pow2_inv_scale(Z);
        m[0] = f4_to_h4(make_float4(u0[0]*s, u0[1]*s, u0[2]*s, u0[3]*s));
    }
    {
        float Z = (u1[0]+u1[1]) + (u1[2]+u1[3]); float s = pow2_inv_scale(Z);
        m[1] = f4_to_h4(make_float4(u1[0]*s, u1[1]*s, u1[2]*s, u1[3]*s));
    }
    {
        float Z = (u2[0]+u2[1]) + (u2[2]+u2[3]); float s = pow2_inv_scale(Z);
        m[2] = f4_to_h4(make_float4(u2[0]*s, u2[1]*s, u2[2]*s, u2[3]*s));
    }
    {
        float Z = (u3[0]+u3[1]) + (u3[2]+u3[3]); float s = pow2_inv_scale(Z);
        m[3] = f4_to_h4(make_float4(u3[0]*s, u3[1]*s, u3[2]*s, u3[3]*s));
    }
}

// ---------------------------------------------------------------------------
// Horizontal-pair ILP-2 iteration: thread handles (i, j0), (i, j0+1), j0 even.
// All neighbor/phi loads are aligned uint4 (LDG.128).
template<int SRC>
__global__ void __launch_bounds__(128) k_iter2h(int nm1) {
    int jp = blockIdx.x * blockDim.x + threadIdx.x;
    int j0 = jp * 2;
    if (j0 >= nm1) return;
    bool jok = (j0 + 1) < nm1;
    int i = blockIdx.y;
    constexpr int DST = SRC ^ 1;

    int q = (i + 1) * SP + j0 + 2;   // even
    uint4 r1 = __ldg((const uint4*)&g_Mh[SRC][1][q - SP]);
    uint4 r0 = __ldg((const uint4*)&g_Mh[SRC][0][q + SP]);
    uint4 r2 = __ldg((const uint4*)&g_Mh[SRC][2][q]);   // right slot2 (shifted)
    uint4 r3 = __ldg((const uint4*)&g_Mh[SRC][3][q]);   // left slot3 (shifted)
    uint4 hT = __ldg((const uint4*)&g_phiEh_h[i * HS + j0]);
    uint4 hB = __ldg((const uint4*)&g_phiEh_h[(i + 1) * HS + j0]);
    uint4 ve  = __ldg((const uint4*)&g_phiEh_v[i * VS + j0]);
    uint2 ve2 = __ldg(&g_phiEh_v[i * VS + j0 + 2]);
    uint4 pa0 = __ldg(&g_phiPh[0][i * HS + j0]);
    uint4 pa1 = __ldg(&g_phiPh[1][i * HS + j0]);

    uint2 mA[4];
    {
        float Phi[16]; phi_unpack(pa0, pa1, Phi);
        float4 N0 = mul4(h4_to_f4(lo4(hT)), h4_to_f4(lo4(r1)));
        float4 N1 = mul4(h4_to_f4(lo4(hB)), h4_to_f4(lo4(r0)));
        float4 N2 = mul4(h4_to_f4(lo4(ve)), h4_to_f4(lo4(r3)));
        float4 N3 = mul4(h4_to_f4(hi4(ve)), h4_to_f4(lo4(r2)));
        plaq_core(N0, N1, N2, N3, Phi, mA);
    }
    if (jok) {
        uint4 pb0 = __ldg(&g_phiPh[0][i * HS + j0 + 1]);
        uint4 pb1 = __ldg(&g_phiPh[1][i * HS + j0 + 1]);
        uint2 mB[4];
        float Phi[16]; phi_unpack(pb0, pb1, Phi);
        float4 N0 = mul4(h4_to_f4(hi4(hT)), h4_to_f4(hi4(r1)));
        float4 N1 = mul4(h4_to_f4(hi4(hB)), h4_to_f4(hi4(r0)));
        float4 N2 = mul4(h4_to_f4(hi4(ve)), h4_to_f4(hi4(r3)));
        float4 N3 = mul4(h4_to_f4(ve2),     h4_to_f4(hi4(r2)));
        plaq_core(N0, N1, N2, N3, Phi, mB);
        *(uint4*)&g_Mh[DST][0][q] = make_uint4(mA[0].x, mA[0].y, mB[0].x, mB[0].y);
        *(uint4*)&g_Mh[DST][1][q] = make_uint4(mA[1].x, mA[1].y, mB[1].x, mB[1].y);
        g_Mh[DST][2][q - 1] = mA[2]; g_Mh[DST][2][q]     = mB[2];
        g_Mh[DST][3][q + 1] = mA[3]; g_Mh[DST][3][q + 2] = mB[3];
    } else {
        g_Mh[DST][0][q]     = mA[0];
        g_Mh[DST][1][q]     = mA[1];
        g_Mh[DST][2][q - 1] = mA[2];
        g_Mh[DST][3][q + 1] = mA[3];
    }
}

// ---------------------------------------------------------------------------
// Fused setup + iteration 1 -> buf 0.  Writes padded fp16 phi tables.
// Last grid.y row: pads + F=0.
__global__ void __launch_bounds__(128) k_first(
    const float4* __restrict__ lpp, const float4* __restrict__ lpe, int nm1)
{
    if (blockIdx.y == gridDim.y - 1) {
        int tot = gridDim.x * blockDim.x;
        int t = blockIdx.x * blockDim.x + threadIdx.x;
        if (t == 0) g_F = 0.0;
        uint2 one = f4_to_h4(make_float4(1.f, 1.f, 1.f, 1.f));
        for (int v = t; v < SP; v += tot) {
            #pragma unroll
            for (int b = 0; b < 2; b++) {
                g_Mh[b][0][(nm1 + 1) * SP + v] = one;   // bottom pad row
                g_Mh[b][1][v] = one;                    // top pad row
                if (v >= 1 && v <= nm1) {
                    g_Mh[b][2][v * SP + nm1 + 1] = one; // right pad col (slot2)
                    g_Mh[b][3][v * SP + 2] = one;       // left pad col (slot3)
                }
            }
        }
        return;
    }

    int pj = blockIdx.x * blockDim.x + threadIdx.x;
    int i0 = blockIdx.y * 2;
    if (pj >= nm1) return;
    int n = nm1 + 1, nH = n * nm1;
    bool iok = (i0 + 1) < nm1;
    int i1 = iok ? i0 + 1 : i0;

    float4 fT  = exp4(__ldg(&lpe[i0 * nm1 + pj]));
    float4 fM  = exp4(__ldg(&lpe[(i0 + 1) * nm1 + pj]));
    float4 fB  = iok ? exp4(__ldg(&lpe[(i0 + 2) * nm1 + pj])) : fM;
    float4 fLA = exp4(__ldg(&lpe[nH + i0 * n + pj]));
    float4 fRA = exp4(__ldg(&lpe[nH + i0 * n + pj + 1]));
    float4 fLB = iok ? exp4(__ldg(&lpe[nH + i1 * n + pj])) : fLA;
    float4 fRB = iok ? exp4(__ldg(&lpe[nH + i1 * n + pj + 1])) : fRA;

    g_phiEh_h[i0 * HS + pj] = f4_to_h4(fT);
    g_phiEh_h[(i0 + 1) * HS + pj] = f4_to_h4(fM);
    g_phiEh_v[i0 * VS + pj] = f4_to_h4(fLA);
    if (iok) g_phiEh_v[i1 * VS + pj] = f4_to_h4(fLB);
    if (pj == nm1 - 1) {
        g_phiEh_v[i0 * VS + nm1] = f4_to_h4(fRA);
        if (iok) g_phiEh_v[i1 * VS + nm1] = f4_to_h4(fRB);
    }

    {   // plaq (i0, pj)
        float Phi[16];
        float4 a = exp4(__ldg(&lpp[(i0 * nm1 + pj) * 4 + 0]));
        float4 b = exp4(__ldg(&lpp[(i0 * nm1 + pj) * 4 + 1]));
        float4 c = exp4(__ldg(&lpp[(i0 * nm1 + pj) * 4 + 2]));
        float4 d = exp4(__ldg(&lpp[(i0 * nm1 + pj) * 4 + 3]));
        Phi[0]=a.x; Phi[1]=a.y; Phi[2]=a.z; Phi[3]=a.w;
        Phi[4]=b.x; Phi[5]=b.y; Phi[6]=b.z; Phi[7]=b.w;
        Phi[8]=c.x; Phi[9]=c.y; Phi[10]=c.z; Phi[11]=c.w;
        Phi[12]=d.x; Phi[13]=d.y; Phi[14]=d.z; Phi[15]=d.w;
        uint2 h0 = f4_to_h4(a), h1 = f4_to_h4(b), h2 = f4_to_h4(c), h3 = f4_to_h4(d);
        g_phiPh[0][i0 * HS + pj] = make_uint4(h0.x, h0.y, h1.x, h1.y);
        g_phiPh[1][i0 * HS + pj] = make_uint4(h2.x, h2.y, h3.x, h3.y);
        uint2 m[4];
        plaq_core(fT, fM, fLA, fRA, Phi, m);
        int q = (i0 + 1) * SP + pj + 2;
        g_Mh[0][0][q] = m[0]; g_Mh[0][1][q] = m[1];
        g_Mh[0][2][q - 1] = m[2]; g_Mh[0][3][q + 1] = m[3];
    }
    if (iok) {   // plaq (i1, pj)
        float Phi[16];
        float4 a = exp4(__ldg(&lpp[(i1 * nm1 + pj) * 4 + 0]));
        float4 b = exp4(__ldg(&lpp[(i1 * nm1 + pj) * 4 + 1]));
        float4 c = exp4(__ldg(&lpp[(i1 * nm1 + pj) * 4 + 2]));
        float4 d = exp4(__ldg(&lpp[(i1 * nm1 + pj) * 4 + 3]));
        Phi[0]=a.x; Phi[1]=a.y; Phi[2]=a.z; Phi[3]=a.w;
        Phi[4]=b.x; Phi[5]=b.y; Phi[6]=b.z; Phi[7]=b.w;
        Phi[8]=c.x; Phi[9]=c.y; Phi[10]=c.z; Phi[11]=c.w;
        Phi[12]=d.x; Phi[13]=d.y; Phi[14]=d.z; Phi[15]=d.w;
        uint2 h0 = f4_to_h4(a), h1 = f4_to_h4(b), h2 = f4_to_h4(c), h3 = f4_to_h4(d);
        g_phiPh[0][i1 * HS + pj] = make_uint4(h0.x, h0.y, h1.x, h1.y);
        g_phiPh[1][i1 * HS + pj] = make_uint4(h2.x, h2.y, h3.x, h3.y);
        uint2 m[4];
        plaq_core(fM, fB, fLB, fRB, Phi, m);
        int q = (i1 + 1) * SP + pj + 2;
        g_Mh[0][0][q] = m[0]; g_Mh[0][1][q] = m[1];
        g_Mh[0][2][q - 1] = m[2]; g_Mh[0][3][q + 1] = m[3];
    }
}

// ---------------------------------------------------------------------------
// Fused finals (reads buf0): h-edge belief, v-edge belief, plaquette F term.
__global__ void k_final(int nm1, const float4* __restrict__ lpe,
                        float* __restrict__ out) {
    int j = blockIdx.x * blockDim.x + threadIdx.x;
    int i = blockIdx.y;
    int n = nm1 + 1, nH = n * nm1;
    float fterm = 0.0f;
    if (j < n) {
        int q = (i + 1) * SP + j + 2;
        float4 m_h0 = h4_to_f4(__ldg(&g_Mh[0][0][q]));
        float4 m_h1 = h4_to_f4(__ldg(&g_Mh[0][1][q - SP]));
        float4 m_v0 = h4_to_f4(__ldg(&g_Mh[0][2][q - 1]));
        float4 m_v1 = h4_to_f4(__ldg(&g_Mh[0][3][q]));
        int outB = 1 + 2 * n * n;

        if (j < nm1) {
            int e = i * nm1 + j;
            float4 lp = __ldg(&lpe[e]);
            float4 pe = exp4(lp);
            float tx = pe.x * m_h0.x * m_h1.x, ty = pe.y * m_h0.y * m_h1.y;
            float tz = pe.z * m_h0.z * m_h1.z, tw = pe.w * m_h0.w * m_h1.w;
            float Z = (tx + ty) + (tz + tw);
            float inv = __fdividef(1.0f, Z);
            float bx = tx * inv, by = ty * inv, bz = tz * inv, bw = tw * inv;
            int base = outB + e * 4;
            out[base + 0] = bx; out[base + 1] = by; out[base + 2] = bz; out[base + 3] = bw;
            if (i > 0 && i < nm1) {
                fterm -= bx * (fast_logf(tx) - lp.x) + by * (fast_logf(ty) - lp.y)
                       + bz * (fast_logf(tz) - lp.z) + bw * (fast_logf(tw) - lp.w)
                       - fast_logf(Z);
            }
        }
        if (i < nm1) {
            int e = nH + i * n + j;
            float4 lp = __ldg(&lpe[e]);
            float4 pe = exp4(lp);
            float tx = pe.x * m_v0.x * m_v1.x, ty = pe.y * m_v0.y * m_v1.y;
            float tz = pe.z * m_v0.z * m_v1.z, tw = pe.w * m_v0.w * m_v1.w;
            float Z = (tx + ty) + (tz + tw);
            float inv = __fdividef(1.0f, Z);
            float bx = tx * inv, by = ty * inv, bz = tz * inv, bw = tw * inv;
            int base = outB + e * 4;
            out[base + 0] = bx; out[base + 1] = by; out[base + 2] = bz; out[base + 3] = bw;
            if (j > 0 && j < nm1) {
                fterm -= bx * (fast_logf(tx) - lp.x) + by * (fast_logf(ty) - lp.y)
                       + bz * (fast_logf(tz) - lp.z) + bw * (fast_logf(tw) - lp.w)
                       - fast_logf(Z);
            }
        }
        if (i < nm1 && j < nm1) {
            float4 N0 = mul4(h4_to_f4(__ldg(&g_phiEh_h[i * HS + j])),       m_h1);
            float4 N1 = mul4(h4_to_f4(__ldg(&g_phiEh_h[(i + 1) * HS + j])),
                             h4_to_f4(__ldg(&g_Mh[0][0][q + SP])));
            float4 N2 = mul4(h4_to_f4(__ldg(&g_phiEh_v[i * VS + j])),       m_v1);
            float4 N3 = mul4(h4_to_f4(__ldg(&g_phiEh_v[i * VS + j + 1])),
                             h4_to_f4(__ldg(&g_Mh[0][2][q])));
            float n0[4] = {N0.x, N0.y, N0.z, N0.w};
            float n1[4] = {N1.x, N1.y, N1.z, N1.w};
            float n2[4] = {N2.x, N2.y, N2.z, N2.w};
            float n3[4] = {N3.x, N3.y, N3.z, N3.w};
            float Phi[16];
            phi_unpack(__ldg(&g_phiPh[0][i * HS + j]), __ldg(&g_phiPh[1][i * HS + j]), Phi);

            float t0[4] = {0,0,0,0}, t1[4] = {0,0,0,0}, t2[4] = {0,0,0,0}, t3[4] = {0,0,0,0};
            #pragma unroll
            for (int a = 0; a < 2; a++)
            #pragma unroll
            for (int b = 0; b < 2; b++)
            #pragma unroll
            for (int c = 0; c < 2; c++)
            #pragma unroll
            for (int d = 0; d < 2; d++) {
                int idx = a * 8 + b * 4 + c * 2 + d;
                float ev = Phi[idx] * n0[a * 2 + b] * n1[c * 2 + d]
                                    * n2[a * 2 + c] * n3[b * 2 + d];
                t0[a * 2 + b] += ev; t1[c * 2 + d] += ev;
                t2[a * 2 + c] += ev; t3[b * 2 + d] += ev;
            }
            float sumE = (t0[0] + t0[1]) + (t0[2] + t0[3]);
            float acc = 0.0f;
            #pragma unroll
            for (int x = 0; x < 4; x++) {
                acc = fmaf(t0[x], fast_logf(n0[x]), acc);
                acc = fmaf(t1[x], fast_logf(n1[x]), acc);
                acc = fmaf(t2[x], fast_logf(n2[x]), acc);
                acc = fmaf(t3[x], fast_logf(n3[x]), acc);
            }
            fterm += __fdividef(acc, sumE) - fast_logf(sumE);
        }
    }
    block_add_F(fterm);
}

// ---------------------------------------------------------------------------
__global__ void k_node(float* __restrict__ out, int n) {
    int j = blockIdx.x * blockDim.x + threadIdx.x;
    int i = blockIdx.y;
    if (i == 0 && j == 0) out[0] = (float)(-g_F);
    if (j >= n) return;
    int nm1 = n - 1, nH = n * nm1;
    const float* B = out + 1 + 2 * n * n;
    float s0 = 0.f, s1 = 0.f; int deg = 0;
    if (j < nm1) { const float* b = B + (i * nm1 + j) * 4;          s0 += b[0] + b[1]; s1 += b[2] + b[3]; deg++; }
    if (j > 0)   { const float* b = B + (i * nm1 + j - 1) * 4;      s0 += b[0] + b[2]; s1 += b[1] + b[3]; deg++; }
    if (i < nm1) { const float* b = B + (nH + i * n + j) * 4;       s0 += b[0] + b[1]; s1 += b[2] + b[3]; deg++; }
    if (i > 0)   { const float* b = B + (nH + (i - 1) * n + j) * 4; s0 += b[0] + b[2]; s1 += b[1] + b[3]; deg++; }
    float invd = __fdividef(1.0f, (float)deg);
    int v = i * n + j;
    out[1 + v * 2 + 0] = s0 * invd;
    out[1 + v * 2 + 1] = s1 * invd;
}

// ---------------------------------------------------------------------------
extern "C" void kernel_launch(void* const* d_in, const int* in_sizes, int n_in,
                              void* d_out, int out_size) {
    const float* log_phi_plaq = (const float*)d_in[0];
    const float* log_phi_edge = (const float*)d_in[1];

    int P = in_sizes[0] / 16;
    int nm1 = (int)lrint(sqrt((double)P));
    int n = nm1 + 1;
    (void)n_in; (void)out_size;
    float* out = (float*)d_out;

    dim3 bs(128);
    dim3 grF((nm1 + 127) / 128, (nm1 + 1) / 2 + 1);  // +1 row for pads
    int pairs = (nm1 + 1) / 2;
    dim3 gr2((pairs + 127) / 128, nm1);              // one plaq-row per grid.y

    // iter 1 (fused with setup) -> buf 0
    k_first<<<grF, bs>>>((const float4*)log_phi_plaq, (const float4*)log_phi_edge, nm1);
    // iters 2..5: 0->1, 1->0, 0->1, 1->0  (final state in buf 0)
    k_iter2h<0><<<gr2, bs>>>(nm1);
    k_iter2h<1><<<gr2, bs>>>(nm1);
    k_iter2h<0><<<gr2, bs>>>(nm1);
    k_iter2h<1><<<gr2, bs>>>(nm1);

    k_final<<<dim3((n + 127) / 128, n), 128>>>(nm1, (const float4*)log_phi_edge, out);
    k_node<<<dim3((n + 127) / 128, n), 128>>>(out, n);
}

// round 9
// speedup vs baseline: 1.1050x; 1.0502x over previous
#include <cuda_runtime.h>
#include <cuda_fp16.h>
#include <math.h>

#define MAXNM1 511
#define MAXSP  (MAXNM1 + 2)
#define MAXSP2 (MAXSP * MAXSP)
#define MAXP   (MAXNM1 * MAXNM1)

// fp16 storage, fp32 compute.
// Messages stored PREMULTIPLIED by sqrt(phiE) of their edge:
//     x(p,s) = sqrt(phiE_s) * m(p,s)   (pow2-normalized)
// Plaquette table holds Psi = phiP * sqrt(phiE0)x(ab) * sqrt(phiE1)x(cd)
//                              * sqrt(phiE2)x(ac) * sqrt(phiE3)x(bd).
// Then E = Psi * prod x, and u_s = sum E / x_s = sqrt(phiE_s)*m_out,s -- the
// stored convention is a fixed point, so iterations need NO edge-phi loads.
// Pads hold sqrt(phiE) of the border edges (cavity with no neighbor).
__device__ uint2 g_Mh[2][4][MAXSP2];   // x messages, padded SoA planes
__device__ uint4 g_psi[2][MAXP];       // Psi as halves (8 states per entry)
__device__ double g_F;

// ---------------------------------------------------------------------------
__device__ __forceinline__ float4 h4_to_f4(uint2 v) {
    union { unsigned u; __half2 h; } a, b;
    a.u = v.x; b.u = v.y;
    float2 fa = __half22float2(a.h), fb = __half22float2(b.h);
    return make_float4(fa.x, fa.y, fb.x, fb.y);
}
__device__ __forceinline__ uint2 f4_to_h4(float4 f) {
    union { unsigned u; __half2 h; } a, b;
    a.h = __floats2half2_rn(f.x, f.y);
    b.h = __floats2half2_rn(f.z, f.w);
    return make_uint2(a.u, b.u);
}

__device__ __forceinline__ float fast_logf(float x) {
    int ix = __float_as_int(x);
    int ex = (ix >> 23) - 127;
    float m = __int_as_float((ix & 0x007FFFFF) | 0x3F800000);
    if (m > 1.41421356f) { m *= 0.5f; ex += 1; }
    float f = m - 1.0f;
    float z = f * f;
    float p = 7.0376836292e-2f;
    p = fmaf(p, f, -1.1514610310e-1f);
    p = fmaf(p, f,  1.1676998740e-1f);
    p = fmaf(p, f, -1.2420140846e-1f);
    p = fmaf(p, f,  1.4249322787e-1f);
    p = fmaf(p, f, -1.6668057665e-1f);
    p = fmaf(p, f,  2.0000714765e-1f);
    p = fmaf(p, f, -2.4999993993e-1f);
    p = fmaf(p, f,  3.3333331174e-1f);
    p = p * z * f;
    p = fmaf(-0.5f, z, p);
    return fmaf((float)ex, 0.693147180559945f, f + p);
}

__device__ __forceinline__ float pow2_inv_scale(float Z) {
    int eb = (__float_as_int(Z) >> 23) & 0xFF;
    return __int_as_float((254 - eb) << 23);
}

__device__ __forceinline__ void block_add_F(float v) {
    #pragma unroll
    for (int o = 16; o; o >>= 1) v += __shfl_down_sync(0xffffffffu, v, o);
    __shared__ float sh[32];
    int lane = threadIdx.x & 31, w = threadIdx.x >> 5;
    if (lane == 0) sh[w] = v;
    __syncthreads();
    if (w == 0) {
        int nw = (blockDim.x + 31) >> 5;
        float s = (lane < nw) ? sh[lane] : 0.0f;
        #pragma unroll
        for (int o = 16; o; o >>= 1) s += __shfl_down_sync(0xffffffffu, s, o);
        if (lane == 0) atomicAdd(&g_F, (double)s);
    }
}

__device__ __forceinline__ float4 mul4(float4 a, float4 b) {
    return make_float4(a.x * b.x, a.y * b.y, a.z * b.z, a.w * b.w);
}
// exp(0.5*v) componentwise = sqrt(phiE) from log-phi
__device__ __forceinline__ float4 exph4f(float4 v) {
    return make_float4(__expf(0.5f * v.x), __expf(0.5f * v.y),
                       __expf(0.5f * v.z), __expf(0.5f * v.w));
}

__device__ __forceinline__ void psi_unpack(int p, float Phi[16]) {
    uint4 q0 = __ldg(&g_psi[0][p]);
    uint4 q1 = __ldg(&g_psi[1][p]);
    float4 a = h4_to_f4(make_uint2(q0.x, q0.y));
    float4 b = h4_to_f4(make_uint2(q0.z, q0.w));
    float4 c = h4_to_f4(make_uint2(q1.x, q1.y));
    float4 d = h4_to_f4(make_uint2(q1.z, q1.w));
    Phi[0]=a.x; Phi[1]=a.y; Phi[2]=a.z; Phi[3]=a.w;
    Phi[4]=b.x; Phi[5]=b.y; Phi[6]=b.z; Phi[7]=b.w;
    Phi[8]=c.x; Phi[9]=c.y; Phi[10]=c.z; Phi[11]=c.w;
    Phi[12]=d.x; Phi[13]=d.y; Phi[14]=d.z; Phi[15]=d.w;
}

// Core 16-state update: cavity x0..x3 + Psi -> normalized messages at offset q.
__device__ __forceinline__ void plaq_update(
    float4 N0, float4 N1, float4 N2, float4 N3, const float Phi[16],
    int dst, int q)
{
    float n0[4] = {N0.x, N0.y, N0.z, N0.w};
    float n1[4] = {N1.x, N1.y, N1.z, N1.w};
    float n2[4] = {N2.x, N2.y, N2.z, N2.w};
    float n3[4] = {N3.x, N3.y, N3.z, N3.w};
    float u0[4] = {0,0,0,0}, u1[4] = {0,0,0,0}, u2[4] = {0,0,0,0}, u3[4] = {0,0,0,0};
    #pragma unroll
    for (int a = 0; a < 2; a++)
    #pragma unroll
    for (int b = 0; b < 2; b++)
    #pragma unroll
    for (int c = 0; c < 2; c++)
    #pragma unroll
    for (int d = 0; d < 2; d++) {
        int idx = a * 8 + b * 4 + c * 2 + d;
        float ph = Phi[idx];
        float va = n0[a * 2 + b], vb = n1[c * 2 + d];
        float vc = n2[a * 2 + c], vd = n3[b * 2 + d];
        float q1 = ph * vc * vd;
        u0[a * 2 + b] = fmaf(q1, vb, u0[a * 2 + b]);
        u1[c * 2 + d] = fmaf(q1, va, u1[c * 2 + d]);
        float q2 = ph * va * vb;
        u2[a * 2 + c] = fmaf(q2, vd, u2[a * 2 + c]);
        u3[b * 2 + d] = fmaf(q2, vc, u3[b * 2 + d]);
    }
    {
        float Z = (u0[0]+u0[1]) + (u0[2]+u0[3]); float s = pow2_inv_scale(Z);
        g_Mh[dst][0][q] = f4_to_h4(make_float4(u0[0]*s, u0[1]*s, u0[2]*s, u0[3]*s));
    }
    {
        float Z = (u1[0]+u1[1]) + (u1[2]+u1[3]); float s = pow2_inv_scale(Z);
        g_Mh[dst][1][q] = f4_to_h4(make_float4(u1[0]*s, u1[1]*s, u1[2]*s, u1[3]*s));
    }
    {
        float Z = (u2[0]+u2[1]) + (u2[2]+u2[3]); float s = pow2_inv_scale(Z);
        g_Mh[dst][2][q] = f4_to_h4(make_float4(u2[0]*s, u2[1]*s, u2[2]*s, u2[3]*s));
    }
    {
        float Z = (u3[0]+u3[1]) + (u3[2]+u3[3]); float s = pow2_inv_scale(Z);
        g_Mh[dst][3][q] = f4_to_h4(make_float4(u3[0]*s, u3[1]*s, u3[2]*s, u3[3]*s));
    }
}

// ---------------------------------------------------------------------------
// ILP-2 iteration (vertical pair, round-6 geometry): NO edge-phi traffic.
template<int SRC>
__global__ void __launch_bounds__(128) k_iter2(int nm1) {
    int pj = blockIdx.x * blockDim.x + threadIdx.x;
    int i0 = blockIdx.y * 2;
    if (pj >= nm1) return;
    int sp = nm1 + 2;
    bool vB = (i0 + 1) < nm1;
    int iB = vB ? (i0 + 1) : i0;
    int pA = i0 * nm1 + pj;
    int pB = iB * nm1 + pj;
    int qA = (i0 + 1) * sp + (pj + 1);
    int qB = (iB + 1) * sp + (pj + 1);

    const uint2* __restrict__ in0 = g_Mh[SRC][0];
    const uint2* __restrict__ in1 = g_Mh[SRC][1];
    const uint2* __restrict__ in2 = g_Mh[SRC][2];
    const uint2* __restrict__ in3 = g_Mh[SRC][3];
    float4 NA0 = h4_to_f4(__ldg(&in1[qA - sp]));
    float4 NA1 = h4_to_f4(__ldg(&in0[qA + sp]));
    float4 NA2 = h4_to_f4(__ldg(&in3[qA - 1]));
    float4 NA3 = h4_to_f4(__ldg(&in2[qA + 1]));
    float4 NB0 = h4_to_f4(__ldg(&in1[qB - sp]));
    float4 NB1 = h4_to_f4(__ldg(&in0[qB + sp]));
    float4 NB2 = h4_to_f4(__ldg(&in3[qB - 1]));
    float4 NB3 = h4_to_f4(__ldg(&in2[qB + 1]));

    constexpr int DST = SRC ^ 1;
    {
        float PhiA[16];
        psi_unpack(pA, PhiA);
        plaq_update(NA0, NA1, NA2, NA3, PhiA, DST, qA);
    }
    if (vB) {
        float PhiB[16];
        psi_unpack(pB, PhiB);
        plaq_update(NB0, NB1, NB2, NB3, PhiB, DST, qB);
    }
}

// ---------------------------------------------------------------------------
// One plaquette of the fused setup+iter1: builds Psi (fp16 table), runs the
// first update with x_in = sqrt(phiE) (uniform initial messages, scale-free).
__device__ __forceinline__ void first_plaq(
    const float4* __restrict__ lpp, int p,
    float4 l0, float4 l1, float4 l2, float4 l3, int q)
{
    float a0[4] = {l0.x, l0.y, l0.z, l0.w};
    float a1[4] = {l1.x, l1.y, l1.z, l1.w};
    float a2[4] = {l2.x, l2.y, l2.z, l2.w};
    float a3[4] = {l3.x, l3.y, l3.z, l3.w};
    float lp[16];
    {
        float4 v;
        v = __ldg(&lpp[p*4+0]); lp[0]=v.x; lp[1]=v.y; lp[2]=v.z; lp[3]=v.w;
        v = __ldg(&lpp[p*4+1]); lp[4]=v.x; lp[5]=v.y; lp[6]=v.z; lp[7]=v.w;
        v = __ldg(&lpp[p*4+2]); lp[8]=v.x; lp[9]=v.y; lp[10]=v.z; lp[11]=v.w;
        v = __ldg(&lpp[p*4+3]); lp[12]=v.x; lp[13]=v.y; lp[14]=v.z; lp[15]=v.w;
    }
    float Phi[16];
    #pragma unroll
    for (int a = 0; a < 2; a++)
    #pragma unroll
    for (int b = 0; b < 2; b++)
    #pragma unroll
    for (int c = 0; c < 2; c++)
    #pragma unroll
    for (int d = 0; d < 2; d++) {
        int idx = a * 8 + b * 4 + c * 2 + d;
        Phi[idx] = __expf(lp[idx] + 0.5f * (a0[a*2+b] + a1[c*2+d]
                                          + a2[a*2+c] + a3[b*2+d]));
    }
    uint2 h0 = f4_to_h4(make_float4(Phi[0],  Phi[1],  Phi[2],  Phi[3]));
    uint2 h1 = f4_to_h4(make_float4(Phi[4],  Phi[5],  Phi[6],  Phi[7]));
    uint2 h2 = f4_to_h4(make_float4(Phi[8],  Phi[9],  Phi[10], Phi[11]));
    uint2 h3 = f4_to_h4(make_float4(Phi[12], Phi[13], Phi[14], Phi[15]));
    g_psi[0][p] = make_uint4(h0.x, h0.y, h1.x, h1.y);
    g_psi[1][p] = make_uint4(h2.x, h2.y, h3.x, h3.y);
    plaq_update(exph4f(l0), exph4f(l1), exph4f(l2), exph4f(l3), Phi, 0, q);
}

// Fused setup + iteration 1 -> buf 0.  Last grid.y row: pads (= sqrt(phiE)
// of border edges, both buffers) + F=0.
__global__ void __launch_bounds__(128) k_first(
    const float4* __restrict__ lpp, const float4* __restrict__ lpe, int nm1)
{
    int sp = nm1 + 2;
    int n = nm1 + 1, nH = n * nm1;
    if (blockIdx.y == gridDim.y - 1) {
        int t = blockIdx.x * blockDim.x + threadIdx.x;
        int tot = gridDim.x * blockDim.x;
        if (t == 0) g_F = 0.0;
        for (int c = t; c < nm1; c += tot) {
            uint2 top = f4_to_h4(exph4f(__ldg(&lpe[c])));
            uint2 bot = f4_to_h4(exph4f(__ldg(&lpe[nm1 * nm1 + c])));
            uint2 lef = f4_to_h4(exph4f(__ldg(&lpe[nH + c * n])));
            uint2 rig = f4_to_h4(exph4f(__ldg(&lpe[nH + c * n + nm1])));
            #pragma unroll
            for (int b = 0; b < 2; b++) {
                g_Mh[b][1][c + 1] = top;                       // row 0 pad
                g_Mh[b][0][(nm1 + 1) * sp + c + 1] = bot;      // bottom pad
                g_Mh[b][3][(c + 1) * sp] = lef;                // left col pad
                g_Mh[b][2][(c + 1) * sp + nm1 + 1] = rig;      // right col pad
            }
        }
        return;
    }

    int pj = blockIdx.x * blockDim.x + threadIdx.x;
    int i0 = blockIdx.y * 2;
    if (pj >= nm1) return;
    bool iok = (i0 + 1) < nm1;
    int i1 = iok ? i0 + 1 : i0;

    float4 lT  = __ldg(&lpe[i0 * nm1 + pj]);
    float4 lM  = __ldg(&lpe[(i0 + 1) * nm1 + pj]);
    float4 lB  = iok ? __ldg(&lpe[(i0 + 2) * nm1 + pj]) : lM;
    float4 lLA = __ldg(&lpe[nH + i0 * n + pj]);
    float4 lRA = __ldg(&lpe[nH + i0 * n + pj + 1]);
    float4 lLB = iok ? __ldg(&lpe[nH + i1 * n + pj]) : lLA;
    float4 lRB = iok ? __ldg(&lpe[nH + i1 * n + pj + 1]) : lRA;

    first_plaq(lpp, i0 * nm1 + pj, lT, lM, lLA, lRA, (i0 + 1) * sp + pj + 1);
    if (iok)
        first_plaq(lpp, i1 * nm1 + pj, lM, lB, lLB, lRB, (i1 + 1) * sp + pj + 1);
}

// ---------------------------------------------------------------------------
// Fused finals (reads buf0): h-edge belief, v-edge belief, plaquette F term.
// Edge beliefs: t = x0*x1 (the two sqrt(phiE) halves reassemble phiE).
__global__ void k_final(int nm1, const float4* __restrict__ lpe,
                        float* __restrict__ out) {
    int j = blockIdx.x * blockDim.x + threadIdx.x;
    int i = blockIdx.y;
    int n = nm1 + 1, sp = nm1 + 2, nH = n * nm1;
    float fterm = 0.0f;
    if (j < n) {
        int q = (i + 1) * sp + j + 1;
        float4 m_h0 = h4_to_f4(__ldg(&g_Mh[0][0][q]));
        float4 m_h1 = h4_to_f4(__ldg(&g_Mh[0][1][q - sp]));
        float4 m_v0 = h4_to_f4(__ldg(&g_Mh[0][2][q]));
        float4 m_v1 = h4_to_f4(__ldg(&g_Mh[0][3][q - 1]));
        int outB = 1 + 2 * n * n;

        float4 lpH = make_float4(0.f, 0.f, 0.f, 0.f);
        float4 lpV = make_float4(0.f, 0.f, 0.f, 0.f);
        if (j < nm1) {
            int e = i * nm1 + j;
            lpH = __ldg(&lpe[e]);
            float tx = m_h0.x * m_h1.x, ty = m_h0.y * m_h1.y;
            float tz = m_h0.z * m_h1.z, tw = m_h0.w * m_h1.w;
            float Z = (tx + ty) + (tz + tw);
            float inv = __fdividef(1.0f, Z);
            float bx = tx * inv, by = ty * inv, bz = tz * inv, bw = tw * inv;
            int base = outB + e * 4;
            out[base + 0] = bx; out[base + 1] = by; out[base + 2] = bz; out[base + 3] = bw;
            if (i > 0 && i < nm1) {
                fterm -= bx * (fast_logf(tx) - lpH.x) + by * (fast_logf(ty) - lpH.y)
                       + bz * (fast_logf(tz) - lpH.z) + bw * (fast_logf(tw) - lpH.w)
                       - fast_logf(Z);
            }
        }
        if (i < nm1) {
            int e = nH + i * n + j;
            lpV = __ldg(&lpe[e]);
            float tx = m_v0.x * m_v1.x, ty = m_v0.y * m_v1.y;
            float tz = m_v0.z * m_v1.z, tw = m_v0.w * m_v1.w;
            float Z = (tx + ty) + (tz + tw);
            float inv = __fdividef(1.0f, Z);
            float bx = tx * inv, by = ty * inv, bz = tz * inv, bw = tw * inv;
            int base = outB + e * 4;
            out[base + 0] = bx; out[base + 1] = by; out[base + 2] = bz; out[base + 3] = bw;
            if (j > 0 && j < nm1) {
                fterm -= bx * (fast_logf(tx) - lpV.x) + by * (fast_logf(ty) - lpV.y)
                       + bz * (fast_logf(tz) - lpV.z) + bw * (fast_logf(tw) - lpV.w)
                       - fast_logf(Z);
            }
        }
        if (i < nm1 && j < nm1) {
            int p = i * nm1 + j;
            // cavity x values (raw stored messages; pads supply sqrt(phiE))
            float4 x0 = m_h1;
            float4 x1 = h4_to_f4(__ldg(&g_Mh[0][0][q + sp]));
            float4 x2 = m_v1;
            float4 x3 = h4_to_f4(__ldg(&g_Mh[0][2][q + 1]));
            // true cavities n = sqrt(phiE)*x for the log terms
            float4 sq0 = exph4f(lpH);
            float4 sq1 = exph4f(__ldg(&lpe[(i + 1) * nm1 + j]));
            float4 sq2 = exph4f(lpV);
            float4 sq3 = exph4f(__ldg(&lpe[nH + i * n + j + 1]));
            float4 Nn0 = mul4(sq0, x0), Nn1 = mul4(sq1, x1);
            float4 Nn2 = mul4(sq2, x2), Nn3 = mul4(sq3, x3);
            float xa[4] = {x0.x, x0.y, x0.z, x0.w};
            float xb[4] = {x1.x, x1.y, x1.z, x1.w};
            float xc[4] = {x2.x, x2.y, x2.z, x2.w};
            float xd[4] = {x3.x, x3.y, x3.z, x3.w};
            float n0[4] = {Nn0.x, Nn0.y, Nn0.z, Nn0.w};
            float n1[4] = {Nn1.x, Nn1.y, Nn1.z, Nn1.w};
            float n2[4] = {Nn2.x, Nn2.y, Nn2.z, Nn2.w};
            float n3[4] = {Nn3.x, Nn3.y, Nn3.z, Nn3.w};
            float Phi[16];
            psi_unpack(p, Phi);

            float t0[4] = {0,0,0,0}, t1[4] = {0,0,0,0}, t2[4] = {0,0,0,0}, t3[4] = {0,0,0,0};
            #pragma unroll
            for (int a = 0; a < 2; a++)
            #pragma unroll
            for (int b = 0; b < 2; b++)
            #pragma unroll
            for (int c = 0; c < 2; c++)
            #pragma unroll
            for (int d = 0; d < 2; d++) {
                int idx = a * 8 + b * 4 + c * 2 + d;
                float ev = Phi[idx] * xa[a * 2 + b] * xb[c * 2 + d]
                                    * xc[a * 2 + c] * xd[b * 2 + d];
                t0[a * 2 + b] += ev; t1[c * 2 + d] += ev;
                t2[a * 2 + c] += ev; t3[b * 2 + d] += ev;
            }
            float sumE = (t0[0] + t0[1]) + (t0[2] + t0[3]);
            float acc = 0.0f;
            #pragma unroll
            for (int x = 0; x < 4; x++) {
                acc = fmaf(t0[x], fast_logf(n0[x]), acc);
                acc = fmaf(t1[x], fast_logf(n1[x]), acc);
                acc = fmaf(t2[x], fast_logf(n2[x]), acc);
                acc = fmaf(t3[x], fast_logf(n3[x]), acc);
            }
            fterm += __fdividef(acc, sumE) - fast_logf(sumE);
        }
    }
    block_add_F(fterm);
}

// ---------------------------------------------------------------------------
__global__ void k_node(float* __restrict__ out, int n) {
    int j = blockIdx.x * blockDim.x + threadIdx.x;
    int i = blockIdx.y;
    if (i == 0 && j == 0) out[0] = (float)(-g_F);
    if (j >= n) return;
    int nm1 = n - 1, nH = n * nm1;
    const float* B = out + 1 + 2 * n * n;
    float s0 = 0.f, s1 = 0.f; int deg = 0;
    if (j < nm1) { const float* b = B + (i * nm1 + j) * 4;          s0 += b[0] + b[1]; s1 += b[2] + b[3]; deg++; }
    if (j > 0)   { const float* b = B + (i * nm1 + j - 1) * 4;      s0 += b[0] + b[2]; s1 += b[1] + b[3]; deg++; }
    if (i < nm1) { const float* b = B + (nH + i * n + j) * 4;       s0 += b[0] + b[1]; s1 += b[2] + b[3]; deg++; }
    if (i > 0)   { const float* b = B + (nH + (i - 1) * n + j) * 4; s0 += b[0] + b[2]; s1 += b[1] + b[3]; deg++; }
    float invd = __fdividef(1.0f, (float)deg);
    int v = i * n + j;
    out[1 + v * 2 + 0] = s0 * invd;
    out[1 + v * 2 + 1] = s1 * invd;
}

// ---------------------------------------------------------------------------
extern "C" void kernel_launch(void* const* d_in, const int* in_sizes, int n_in,
                              void* d_out, int out_size) {
    const float* log_phi_plaq = (const float*)d_in[0];
    const float* log_phi_edge = (const float*)d_in[1];

    int P = in_sizes[0] / 16;
    int nm1 = (int)lrint(sqrt((double)P));
    int n = nm1 + 1;
    (void)n_in; (void)out_size;
    float* out = (float*)d_out;

    dim3 bs(128);
    dim3 grF((nm1 + 127) / 128, (nm1 + 1) / 2 + 1);  // +1 row for pads
    dim3 gr((nm1 + 127) / 128, (nm1 + 1) / 2);

    // iter 1 (fused with setup) -> buf 0
    k_first<<<grF, bs>>>((const float4*)log_phi_plaq, (const float4*)log_phi_edge, nm1);
    // iters 2..5: 0->1, 1->0, 0->1, 1->0  (final state in buf 0)
    k_iter2<0><<<gr, bs>>>(nm1);
    k_iter2<1><<<gr, bs>>>(nm1);
    k_iter2<0><<<gr, bs>>>(nm1);
    k_iter2<1><<<gr, bs>>>(nm1);

    k_final<<<dim3((n + 127) / 128, n), 128>>>(nm1, (const float4*)log_phi_edge, out);
    k_node<<<dim3((n + 127) / 128, n), 128>>>(out, n);
}

// round 11
// speedup vs baseline: 1.1540x; 1.0444x over previous
#include <cuda_runtime.h>
#include <cuda_fp16.h>
#include <math.h>

#define MAXNM1 511
#define MAXSP  (MAXNM1 + 2)
#define MAXSP2 (MAXSP * MAXSP)
#define MAXP   (MAXNM1 * MAXNM1)

// fp16 storage, fp32 compute.
// Messages stored PREMULTIPLIED by sqrt(phiE) of their edge:
//     x(p,s) = sqrt(phiE_s) * m(p,s)   (pow2-normalized)
// Plaquette table holds Psi = phiP * prod_s sqrt(phiE_s).
// E = Psi * prod x; u_s = sum E / x_s = sqrt(phiE_s)*m_out,s — the stored
// convention is a fixed point, so iterations need NO edge-phi traffic.
// Pads hold sqrt(phiE) of the border edges.
__device__ uint2 g_Mh[2][4][MAXSP2];   // x messages, padded SoA planes
__device__ uint4 g_psi[2][MAXP];       // Psi as halves (8 states per entry)
__device__ double g_F;
__device__ unsigned g_ctr;

// ---------------------------------------------------------------------------
__device__ __forceinline__ float4 h4_to_f4(uint2 v) {
    union { unsigned u; __half2 h; } a, b;
    a.u = v.x; b.u = v.y;
    float2 fa = __half22float2(a.h), fb = __half22float2(b.h);
    return make_float4(fa.x, fa.y, fb.x, fb.y);
}
__device__ __forceinline__ uint2 f4_to_h4(float4 f) {
    union { unsigned u; __half2 h; } a, b;
    a.h = __floats2half2_rn(f.x, f.y);
    b.h = __floats2half2_rn(f.z, f.w);
    return make_uint2(a.u, b.u);
}

__device__ __forceinline__ float fast_logf(float x) {
    int ix = __float_as_int(x);
    int ex = (ix >> 23) - 127;
    float m = __int_as_float((ix & 0x007FFFFF) | 0x3F800000);
    if (m > 1.41421356f) { m *= 0.5f; ex += 1; }
    float f = m - 1.0f;
    float z = f * f;
    float p = 7.0376836292e-2f;
    p = fmaf(p, f, -1.1514610310e-1f);
    p = fmaf(p, f,  1.1676998740e-1f);
    p = fmaf(p, f, -1.2420140846e-1f);
    p = fmaf(p, f,  1.4249322787e-1f);
    p = fmaf(p, f, -1.6668057665e-1f);
    p = fmaf(p, f,  2.0000714765e-1f);
    p = fmaf(p, f, -2.4999993993e-1f);
    p = fmaf(p, f,  3.3333331174e-1f);
    p = p * z * f;
    p = fmaf(-0.5f, z, p);
    return fmaf((float)ex, 0.693147180559945f, f + p);
}

__device__ __forceinline__ float pow2_inv_scale(float Z) {
    int eb = (__float_as_int(Z) >> 23) & 0xFF;
    return __int_as_float((254 - eb) << 23);
}

__device__ __forceinline__ void block_add_F(float v) {
    #pragma unroll
    for (int o = 16; o; o >>= 1) v += __shfl_down_sync(0xffffffffu, v, o);
    __shared__ float sh[32];
    int lane = threadIdx.x & 31, w = threadIdx.x >> 5;
    if (lane == 0) sh[w] = v;
    __syncthreads();
    if (w == 0) {
        int nw = (blockDim.x + 31) >> 5;
        float s = (lane < nw) ? sh[lane] : 0.0f;
        #pragma unroll
        for (int o = 16; o; o >>= 1) s += __shfl_down_sync(0xffffffffu, s, o);
        if (lane == 0) atomicAdd(&g_F, (double)s);
    }
}

__device__ __forceinline__ float4 mul4(float4 a, float4 b) {
    return make_float4(a.x * b.x, a.y * b.y, a.z * b.z, a.w * b.w);
}
__device__ __forceinline__ float4 exph4f(float4 v) {
    return make_float4(__expf(0.5f * v.x), __expf(0.5f * v.y),
                       __expf(0.5f * v.z), __expf(0.5f * v.w));
}

__device__ __forceinline__ void psi_unpack(int p, float Phi[16]) {
    uint4 q0 = __ldg(&g_psi[0][p]);
    uint4 q1 = __ldg(&g_psi[1][p]);
    float4 a = h4_to_f4(make_uint2(q0.x, q0.y));
    float4 b = h4_to_f4(make_uint2(q0.z, q0.w));
    float4 c = h4_to_f4(make_uint2(q1.x, q1.y));
    float4 d = h4_to_f4(make_uint2(q1.z, q1.w));
    Phi[0]=a.x; Phi[1]=a.y; Phi[2]=a.z; Phi[3]=a.w;
    Phi[4]=b.x; Phi[5]=b.y; Phi[6]=b.z; Phi[7]=b.w;
    Phi[8]=c.x; Phi[9]=c.y; Phi[10]=c.z; Phi[11]=c.w;
    Phi[12]=d.x; Phi[13]=d.y; Phi[14]=d.z; Phi[15]=d.w;
}

// Core 16-state update: cavity x0..x3 + Psi -> normalized messages at offset q.
__device__ __forceinline__ void plaq_update(
    float4 N0, float4 N1, float4 N2, float4 N3, const float Phi[16],
    int dst, int q)
{
    float n0[4] = {N0.x, N0.y, N0.z, N0.w};
    float n1[4] = {N1.x, N1.y, N1.z, N1.w};
    float n2[4] = {N2.x, N2.y, N2.z, N2.w};
    float n3[4] = {N3.x, N3.y, N3.z, N3.w};
    float u0[4] = {0,0,0,0}, u1[4] = {0,0,0,0}, u2[4] = {0,0,0,0}, u3[4] = {0,0,0,0};
    #pragma unroll
    for (int a = 0; a < 2; a++)
    #pragma unroll
    for (int b = 0; b < 2; b++)
    #pragma unroll
    for (int c = 0; c < 2; c++)
    #pragma unroll
    for (int d = 0; d < 2; d++) {
        int idx = a * 8 + b * 4 + c * 2 + d;
        float ph = Phi[idx];
        float va = n0[a * 2 + b], vb = n1[c * 2 + d];
        float vc = n2[a * 2 + c], vd = n3[b * 2 + d];
        float q1 = ph * vc * vd;
        u0[a * 2 + b] = fmaf(q1, vb, u0[a * 2 + b]);
        u1[c * 2 + d] = fmaf(q1, va, u1[c * 2 + d]);
        float q2 = ph * va * vb;
        u2[a * 2 + c] = fmaf(q2, vd, u2[a * 2 + c]);
        u3[b * 2 + d] = fmaf(q2, vc, u3[b * 2 + d]);
    }
    {
        float Z = (u0[0]+u0[1]) + (u0[2]+u0[3]); float s = pow2_inv_scale(Z);
        g_Mh[dst][0][q] = f4_to_h4(make_float4(u0[0]*s, u0[1]*s, u0[2]*s, u0[3]*s));
    }
    {
        float Z = (u1[0]+u1[1]) + (u1[2]+u1[3]); float s = pow2_inv_scale(Z);
        g_Mh[dst][1][q] = f4_to_h4(make_float4(u1[0]*s, u1[1]*s, u1[2]*s, u1[3]*s));
    }
    {
        float Z = (u2[0]+u2[1]) + (u2[2]+u2[3]); float s = pow2_inv_scale(Z);
        g_Mh[dst][2][q] = f4_to_h4(make_float4(u2[0]*s, u2[1]*s, u2[2]*s, u2[3]*s));
    }
    {
        float Z = (u3[0]+u3[1]) + (u3[2]+u3[3]); float s = pow2_inv_scale(Z);
        g_Mh[dst][3][q] = f4_to_h4(make_float4(u3[0]*s, u3[1]*s, u3[2]*s, u3[3]*s));
    }
}

// ---------------------------------------------------------------------------
// ILP-2 iteration (vertical pair): NO edge-phi traffic.
template<int SRC>
__global__ void __launch_bounds__(128) k_iter2(int nm1) {
    int pj = blockIdx.x * blockDim.x + threadIdx.x;
    int i0 = blockIdx.y * 2;
    if (pj >= nm1) return;
    int sp = nm1 + 2;
    bool vB = (i0 + 1) < nm1;
    int iB = vB ? (i0 + 1) : i0;
    int pA = i0 * nm1 + pj;
    int pB = iB * nm1 + pj;
    int qA = (i0 + 1) * sp + (pj + 1);
    int qB = (iB + 1) * sp + (pj + 1);

    const uint2* __restrict__ in0 = g_Mh[SRC][0];
    const uint2* __restrict__ in1 = g_Mh[SRC][1];
    const uint2* __restrict__ in2 = g_Mh[SRC][2];
    const uint2* __restrict__ in3 = g_Mh[SRC][3];
    float4 NA0 = h4_to_f4(__ldg(&in1[qA - sp]));
    float4 NA1 = h4_to_f4(__ldg(&in0[qA + sp]));
    float4 NA2 = h4_to_f4(__ldg(&in3[qA - 1]));
    float4 NA3 = h4_to_f4(__ldg(&in2[qA + 1]));
    float4 NB0 = h4_to_f4(__ldg(&in1[qB - sp]));
    float4 NB1 = h4_to_f4(__ldg(&in0[qB + sp]));
    float4 NB2 = h4_to_f4(__ldg(&in3[qB - 1]));
    float4 NB3 = h4_to_f4(__ldg(&in2[qB + 1]));

    constexpr int DST = SRC ^ 1;
    {
        float PhiA[16];
        psi_unpack(pA, PhiA);
        plaq_update(NA0, NA1, NA2, NA3, PhiA, DST, qA);
    }
    if (vB) {
        float PhiB[16];
        psi_unpack(pB, PhiB);
        plaq_update(NB0, NB1, NB2, NB3, PhiB, DST, qB);
    }
}

// ---------------------------------------------------------------------------
__device__ __forceinline__ void first_plaq(
    const float4* __restrict__ lpp, int p,
    float4 l0, float4 l1, float4 l2, float4 l3, int q)
{
    float a0[4] = {l0.x, l0.y, l0.z, l0.w};
    float a1[4] = {l1.x, l1.y, l1.z, l1.w};
    float a2[4] = {l2.x, l2.y, l2.z, l2.w};
    float a3[4] = {l3.x, l3.y, l3.z, l3.w};
    float lp[16];
    {
        float4 v;
        v = __ldg(&lpp[p*4+0]); lp[0]=v.x; lp[1]=v.y; lp[2]=v.z; lp[3]=v.w;
        v = __ldg(&lpp[p*4+1]); lp[4]=v.x; lp[5]=v.y; lp[6]=v.z; lp[7]=v.w;
        v = __ldg(&lpp[p*4+2]); lp[8]=v.x; lp[9]=v.y; lp[10]=v.z; lp[11]=v.w;
        v = __ldg(&lpp[p*4+3]); lp[12]=v.x; lp[13]=v.y; lp[14]=v.z; lp[15]=v.w;
    }
    float Phi[16];
    #pragma unroll
    for (int a = 0; a < 2; a++)
    #pragma unroll
    for (int b = 0; b < 2; b++)
    #pragma unroll
    for (int c = 0; c < 2; c++)
    #pragma unroll
    for (int d = 0; d < 2; d++) {
        int idx = a * 8 + b * 4 + c * 2 + d;
        Phi[idx] = __expf(lp[idx] + 0.5f * (a0[a*2+b] + a1[c*2+d]
                                          + a2[a*2+c] + a3[b*2+d]));
    }
    uint2 h0 = f4_to_h4(make_float4(Phi[0],  Phi[1],  Phi[2],  Phi[3]));
    uint2 h1 = f4_to_h4(make_float4(Phi[4],  Phi[5],  Phi[6],  Phi[7]));
    uint2 h2 = f4_to_h4(make_float4(Phi[8],  Phi[9],  Phi[10], Phi[11]));
    uint2 h3 = f4_to_h4(make_float4(Phi[12], Phi[13], Phi[14], Phi[15]));
    g_psi[0][p] = make_uint4(h0.x, h0.y, h1.x, h1.y);
    g_psi[1][p] = make_uint4(h2.x, h2.y, h3.x, h3.y);
    plaq_update(exph4f(l0), exph4f(l1), exph4f(l2), exph4f(l3), Phi, 0, q);
}

// Fused setup + iteration 1 -> buf 0.  Last grid.y row: pads + F=0 + ctr=0.
__global__ void __launch_bounds__(128) k_first(
    const float4* __restrict__ lpp, const float4* __restrict__ lpe, int nm1)
{
    int sp = nm1 + 2;
    int n = nm1 + 1, nH = n * nm1;
    if (blockIdx.y == gridDim.y - 1) {
        int t = blockIdx.x * blockDim.x + threadIdx.x;
        int tot = gridDim.x * blockDim.x;
        if (t == 0) { g_F = 0.0; g_ctr = 0u; }
        for (int c = t; c < nm1; c += tot) {
            uint2 top = f4_to_h4(exph4f(__ldg(&lpe[c])));
            uint2 bot = f4_to_h4(exph4f(__ldg(&lpe[nm1 * nm1 + c])));
            uint2 lef = f4_to_h4(exph4f(__ldg(&lpe[nH + c * n])));
            uint2 rig = f4_to_h4(exph4f(__ldg(&lpe[nH + c * n + nm1])));
            #pragma unroll
            for (int b = 0; b < 2; b++) {
                g_Mh[b][1][c + 1] = top;                       // row 0 pad
                g_Mh[b][0][(nm1 + 1) * sp + c + 1] = bot;      // bottom pad
                g_Mh[b][3][(c + 1) * sp] = lef;                // left col pad
                g_Mh[b][2][(c + 1) * sp + nm1 + 1] = rig;      // right col pad
            }
        }
        return;
    }

    int pj = blockIdx.x * blockDim.x + threadIdx.x;
    int i0 = blockIdx.y * 2;
    if (pj >= nm1) return;
    bool iok = (i0 + 1) < nm1;
    int i1 = iok ? i0 + 1 : i0;

    float4 lT  = __ldg(&lpe[i0 * nm1 + pj]);
    float4 lM  = __ldg(&lpe[(i0 + 1) * nm1 + pj]);
    float4 lB  = iok ? __ldg(&lpe[(i0 + 2) * nm1 + pj]) : lM;
    float4 lLA = __ldg(&lpe[nH + i0 * n + pj]);
    float4 lRA = __ldg(&lpe[nH + i0 * n + pj + 1]);
    float4 lLB = iok ? __ldg(&lpe[nH + i1 * n + pj]) : lLA;
    float4 lRB = iok ? __ldg(&lpe[nH + i1 * n + pj + 1]) : lRA;

    first_plaq(lpp, i0 * nm1 + pj, lT, lM, lLA, lRA, (i0 + 1) * sp + pj + 1);
    if (iok)
        first_plaq(lpp, i1 * nm1 + pj, lM, lB, lLB, lRB, (i1 + 1) * sp + pj + 1);
}

// ---------------------------------------------------------------------------
// Fully fused finals (reads buf0): per (i,j) computes h/v edge beliefs,
// plaquette F term, AND the node's unary marginal (recomputing the left/top
// incident edge beliefs from 4 extra message loads). Last finished block
// writes out[0] = -F.
__global__ void k_final(int nm1, const float4* __restrict__ lpe,
                        float* __restrict__ out) {
    int j = blockIdx.x * blockDim.x + threadIdx.x;
    int i = blockIdx.y;
    int n = nm1 + 1, sp = nm1 + 2, nH = n * nm1;
    float fterm = 0.0f;
    if (j < n) {
        int q = (i + 1) * sp + j + 1;
        float4 m_h0 = h4_to_f4(__ldg(&g_Mh[0][0][q]));
        float4 m_h1 = h4_to_f4(__ldg(&g_Mh[0][1][q - sp]));
        float4 m_v0 = h4_to_f4(__ldg(&g_Mh[0][2][q]));
        float4 m_v1 = h4_to_f4(__ldg(&g_Mh[0][3][q - 1]));
        int outB = 1 + 2 * n * n;

        float s0 = 0.f, s1 = 0.f;
        int deg = 0;

        float4 lpH = make_float4(0.f, 0.f, 0.f, 0.f);
        float4 lpV = make_float4(0.f, 0.f, 0.f, 0.f);
        if (j < nm1) {      // h-edge (i,j): write belief + node var0 contrib
            int e = i * nm1 + j;
            lpH = __ldg(&lpe[e]);
            float tx = m_h0.x * m_h1.x, ty = m_h0.y * m_h1.y;
            float tz = m_h0.z * m_h1.z, tw = m_h0.w * m_h1.w;
            float Z = (tx + ty) + (tz + tw);
            float inv = __fdividef(1.0f, Z);
            float bx = tx * inv, by = ty * inv, bz = tz * inv, bw = tw * inv;
            int base = outB + e * 4;
            out[base + 0] = bx; out[base + 1] = by; out[base + 2] = bz; out[base + 3] = bw;
            s0 += bx + by; s1 += bz + bw; deg++;
            if (i > 0 && i < nm1) {
                fterm -= bx * (fast_logf(tx) - lpH.x) + by * (fast_logf(ty) - lpH.y)
                       + bz * (fast_logf(tz) - lpH.z) + bw * (fast_logf(tw) - lpH.w)
                       - fast_logf(Z);
            }
        }
        if (j > 0) {        // h-edge (i,j-1): node var1 contrib (recompute)
            float4 a = h4_to_f4(__ldg(&g_Mh[0][0][q - 1]));
            float4 b = h4_to_f4(__ldg(&g_Mh[0][1][q - sp - 1]));
            float tx = a.x * b.x, ty = a.y * b.y, tz = a.z * b.z, tw = a.w * b.w;
            float inv = __fdividef(1.0f, (tx + ty) + (tz + tw));
            s0 += (tx + tz) * inv; s1 += (ty + tw) * inv; deg++;
        }
        if (i < nm1) {      // v-edge (i,j): write belief + node var0 contrib
            int e = nH + i * n + j;
            lpV = __ldg(&lpe[e]);
            float tx = m_v0.x * m_v1.x, ty = m_v0.y * m_v1.y;
            float tz = m_v0.z * m_v1.z, tw = m_v0.w * m_v1.w;
            float Z = (tx + ty) + (tz + tw);
            float inv = __fdividef(1.0f, Z);
            float bx = tx * inv, by = ty * inv, bz = tz * inv, bw = tw * inv;
            int base = outB + e * 4;
            out[base + 0] = bx; out[base + 1] = by; out[base + 2] = bz; out[base + 3] = bw;
            s0 += bx + by; s1 += bz + bw; deg++;
            if (j > 0 && j < nm1) {
                fterm -= bx * (fast_logf(tx) - lpV.x) + by * (fast_logf(ty) - lpV.y)
                       + bz * (fast_logf(tz) - lpV.z) + bw * (fast_logf(tw) - lpV.w)
                       - fast_logf(Z);
            }
        }
        if (i > 0) {        // v-edge (i-1,j): node var1 contrib (recompute)
            float4 a = h4_to_f4(__ldg(&g_Mh[0][2][q - sp]));
            float4 b = h4_to_f4(__ldg(&g_Mh[0][3][q - sp - 1]));
            float tx = a.x * b.x, ty = a.y * b.y, tz = a.z * b.z, tw = a.w * b.w;
            float inv = __fdividef(1.0f, (tx + ty) + (tz + tw));
            s0 += (tx + tz) * inv; s1 += (ty + tw) * inv; deg++;
        }
        {   // unary marginal
            float invd = __fdividef(1.0f, (float)deg);
            int v = i * n + j;
            out[1 + v * 2 + 0] = s0 * invd;
            out[1 + v * 2 + 1] = s1 * invd;
        }

        if (i < nm1 && j < nm1) {   // plaquette F term
            int p = i * nm1 + j;
            float4 x0 = m_h1;
            float4 x1 = h4_to_f4(__ldg(&g_Mh[0][0][q + sp]));
            float4 x2 = m_v1;
            float4 x3 = h4_to_f4(__ldg(&g_Mh[0][2][q + 1]));
            float4 sq0 = exph4f(lpH);
            float4 sq1 = exph4f(__ldg(&lpe[(i + 1) * nm1 + j]));
            float4 sq2 = exph4f(lpV);
            float4 sq3 = exph4f(__ldg(&lpe[nH + i * n + j + 1]));
            float4 Nn0 = mul4(sq0, x0), Nn1 = mul4(sq1, x1);
            float4 Nn2 = mul4(sq2, x2), Nn3 = mul4(sq3, x3);
            float xa[4] = {x0.x, x0.y, x0.z, x0.w};
            float xb[4] = {x1.x, x1.y, x1.z, x1.w};
            float xc[4] = {x2.x, x2.y, x2.z, x2.w};
            float xd[4] = {x3.x, x3.y, x3.z, x3.w};
            float n0[4] = {Nn0.x, Nn0.y, Nn0.z, Nn0.w};
            float n1[4] = {Nn1.x, Nn1.y, Nn1.z, Nn1.w};
            float n2[4] = {Nn2.x, Nn2.y, Nn2.z, Nn2.w};
            float n3[4] = {Nn3.x, Nn3.y, Nn3.z, Nn3.w};
            float Phi[16];
            psi_unpack(p, Phi);

            float t0[4] = {0,0,0,0}, t1[4] = {0,0,0,0}, t2[4] = {0,0,0,0}, t3[4] = {0,0,0,0};
            #pragma unroll
            for (int a = 0; a < 2; a++)
            #pragma unroll
            for (int b = 0; b < 2; b++)
            #pragma unroll
            for (int c = 0; c < 2; c++)
            #pragma unroll
            for (int d = 0; d < 2; d++) {
                int idx = a * 8 + b * 4 + c * 2 + d;
                float ev = Phi[idx] * xa[a * 2 + b] * xb[c * 2 + d]
                                    * xc[a * 2 + c] * xd[b * 2 + d];
                t0[a * 2 + b] += ev; t1[c * 2 + d] += ev;
                t2[a * 2 + c] += ev; t3[b * 2 + d] += ev;
            }
            float sumE = (t0[0] + t0[1]) + (t0[2] + t0[3]);
            float acc = 0.0f;
            #pragma unroll
            for (int x = 0; x < 4; x++) {
                acc = fmaf(t0[x], fast_logf(n0[x]), acc);
                acc = fmaf(t1[x], fast_logf(n1[x]), acc);
                acc = fmaf(t2[x], fast_logf(n2[x]), acc);
                acc = fmaf(t3[x], fast_logf(n3[x]), acc);
            }
            fterm += __fdividef(acc, sumE) - fast_logf(sumE);
        }
    }
    block_add_F(fterm);

    // Last-block-done: write -F once all blocks' g_F adds are visible.
    __syncthreads();
    if (threadIdx.x == 0) {
        __threadfence();
        unsigned total = gridDim.x * gridDim.y;
        unsigned old = atomicAdd(&g_ctr, 1u);
        if (old == total - 1) {
            double F = atomicAdd(&g_F, 0.0);   // RMW: total order per address
            out[0] = (float)(-F);
        }
    }
}

// ---------------------------------------------------------------------------
extern "C" void kernel_launch(void* const* d_in, const int* in_sizes, int n_in,
                              void* d_out, int out_size) {
    const float* log_phi_plaq = (const float*)d_in[0];
    const float* log_phi_edge = (const float*)d_in[1];

    int P = in_sizes[0] / 16;
    int nm1 = (int)lrint(sqrt((double)P));
    int n = nm1 + 1;
    (void)n_in; (void)out_size;
    float* out = (float*)d_out;

    dim3 bs(128);
    dim3 grF((nm1 + 127) / 128, (nm1 + 1) / 2 + 1);  // +1 row for pads
    dim3 gr((nm1 + 127) / 128, (nm1 + 1) / 2);

    // iter 1 (fused with setup) -> buf 0
    k_first<<<grF, bs>>>((const float4*)log_phi_plaq, (const float4*)log_phi_edge, nm1);
    // iters 2..5: 0->1, 1->0, 0->1, 1->0  (final state in buf 0)
    k_iter2<0><<<gr, bs>>>(nm1);
    k_iter2<1><<<gr, bs>>>(nm1);
    k_iter2<0><<<gr, bs>>>(nm1);
    k_iter2<1><<<gr, bs>>>(nm1);

    k_final<<<dim3((n + 127) / 128, n), 128>>>(nm1, (const float4*)log_phi_edge, out);
}